// round 11
// baseline (speedup 1.0000x reference)
#include <cuda_runtime.h>
#include <cuda_fp16.h>
#include <cstdint>

// ============================================================================
// GaussianMLP fused — sm_103 plain target, fp16 mma.sync.m16n8k16.
// R11: PERSISTENT CTAs (grid=152), W2 resident in SMEM (loaded once/CTA),
//      W1 2-slot ring prefetched during layer 2, interleaved mean/logvar W2
//      columns -> register-only epilogue (no SMEM exchange).
//      512 thr, 16 warps, warp tile M32xN64.
// ============================================================================

#define NTILES 4096
#define GRID   152

__device__ __forceinline__ uint32_t smem_u32(const void* p) {
    uint32_t a;
    asm("{ .reg .u64 t; cvta.to.shared.u64 t, %1; cvt.u32.u64 %0, t; }" : "=r"(a) : "l"(p));
    return a;
}
__device__ __forceinline__ void mma16(float* c, const uint32_t* a, uint32_t b0, uint32_t b1) {
    asm volatile(
        "mma.sync.aligned.m16n8k16.row.col.f32.f16.f16.f32 "
        "{%0,%1,%2,%3},{%4,%5,%6,%7},{%8,%9},{%0,%1,%2,%3};"
        : "+f"(c[0]), "+f"(c[1]), "+f"(c[2]), "+f"(c[3])
        : "r"(a[0]), "r"(a[1]), "r"(a[2]), "r"(a[3]), "r"(b0), "r"(b1));
}
__device__ __forceinline__ void ldsm4(uint32_t* r, uint32_t addr) {
    asm volatile("ldmatrix.sync.aligned.m8n8.x4.shared.b16 {%0,%1,%2,%3}, [%4];"
                 : "=r"(r[0]), "=r"(r[1]), "=r"(r[2]), "=r"(r[3]) : "r"(addr));
}
#define CP16CG(dst, src) \
    asm volatile("cp.async.cg.shared.global [%0], [%1], 16;" :: "r"(dst), "l"(src))
#define CP_COMMIT() asm volatile("cp.async.commit_group;" ::: "memory")
#define CP_WAIT1()  asm volatile("cp.async.wait_group 1;" ::: "memory")
#define CP_WAIT0()  asm volatile("cp.async.wait_group 0;" ::: "memory")

// ---------------- device-global prepared weights -----------------------------
__device__ __align__(16) __half g_wemb_h[256 * 128];   // [n][k]  n: h col
__device__ __align__(16) __half g_w2_h[256 * 256];     // [n'][k] n' interleaved:
                                                       //  n'=2c -> W_mean col c, n'=2c+1 -> W_logvar col c
__global__ void prep_kernel(const float* __restrict__ We,
                            const float* __restrict__ Wm,
                            const float* __restrict__ Wl) {
    int i = blockIdx.x * 256 + threadIdx.x;
    if (i < 32768) {
        int n = i >> 7, k = i & 127;
        g_wemb_h[i] = __float2half(We[k * 256 + n]);
    } else if (i < 98304) {
        int j = i - 32768;
        int np = j >> 8, k = j & 255;
        int c = np >> 1;
        float v = (np & 1) ? Wl[k * 128 + c] : Wm[k * 128 + c];
        g_w2_h[j] = __float2half(v);
    }
}

// ---------------- SMEM map (231424 B) ----------------------------------------
// W2   : [256 n'][512B] seg-swizzled                 131072
// hs   : x [128][256B] (L1) -> h [128][512B] (L2)     65536
// ring : W1 2 slots x [128 rowpairs][128B]            32768
// bias : 2048
#define W2_OFF   0u
#define HS_OFF   131072u
#define R0_OFF   196608u
#define R1_OFF   212992u
#define SBE_OFF  229376u
#define SBM_OFF  230400u
#define SBL_OFF  230912u
#define SMEM_TOTAL 231424

__global__ void __launch_bounds__(512, 1)
gauss_kernel(const float* __restrict__ x, const float* __restrict__ eps,
             const float* __restrict__ be, const float* __restrict__ bm,
             const float* __restrict__ bl, float* __restrict__ out) {
    extern __shared__ char smem[];
    const uint32_t sm = smem_u32(smem);
    float* sbe = (float*)(smem + SBE_OFF);
    float* sbm = (float*)(smem + SBM_OFF);
    float* sbl = (float*)(smem + SBL_OFF);

    const int tid  = threadIdx.x;
    const int wid  = tid >> 5, lane = tid & 31;
    const int g    = lane >> 2, tg = lane & 3;
    const int mw   = wid & 3;                 // M block (32 rows)
    const int nw   = wid >> 2;                // N block (64 of 256 interleaved)
    const int nb   = nw * 64;
    const int fr_row = lane & 15;
    const int fr_k8  = (lane >> 4) & 1;       // k-seg offset (0/1)

    if (tid < 256) sbe[tid] = be[tid];
    if (tid < 128) { sbm[tid] = bm[tid]; sbl[tid] = bl[tid]; }

    // ---- persistent W2 load (once): seg-swizzled 512B rows ------------------
    {
        #pragma unroll
        for (int j = 0; j < 16; j++) {
            int s_i = tid + j * 512;
            int row = s_i >> 5, seg = s_i & 31;
            CP16CG(sm + W2_OFF + (uint32_t)(row * 512) + (uint32_t)((seg ^ (row & 7)) << 4),
                   g_w2_h + row * 256 + seg * 8);
        }
        CP_COMMIT();
    }
    // W1 chunk issuer: chunk cc (K=32 halves) -> row-pair 128B-atom layout
    auto issue_w1 = [&](int cc, uint32_t slot) {
        #pragma unroll
        for (int j = 0; j < 2; j++) {
            int s_i = tid + j * 512;               // 1024 segs
            int p = s_i >> 3, s8 = s_i & 7;
            int n = 2 * p + (s8 >> 2), sg = s8 & 3;
            CP16CG(slot + (uint32_t)(p * 128) + (uint32_t)((s8 ^ (p & 7)) << 4),
                   g_wemb_h + n * 128 + cc * 32 + sg * 8);
        }
        CP_COMMIT();
    };
    issue_w1(0, sm + R0_OFF);
    issue_w1(1, sm + R1_OFF);

    // ---- per-lane loop invariants -------------------------------------------
    const int arow0 = mw * 32 + fr_row, arow1 = arow0 + 16;
    const uint32_t xA0 = sm + HS_OFF + (uint32_t)(arow0 * 256), xsw0 = (uint32_t)((arow0 & 7) << 4);
    const uint32_t xA1 = sm + HS_OFF + (uint32_t)(arow1 * 256), xsw1 = (uint32_t)((arow1 & 7) << 4);
    const uint32_t hA0 = sm + HS_OFF + (uint32_t)(arow0 * 512);
    const uint32_t hA1 = sm + HS_OFF + (uint32_t)(arow1 * 512);
    uint32_t w1b[4], w2b[4], w2sw[4];
    #pragma unroll
    for (int q = 0; q < 4; q++) {
        int n = nb + q * 16 + fr_row;              // W1 B row
        int p = n >> 1;
        w1b[q] = (uint32_t)(p * 128) | ((uint32_t)(((n & 1) << 2) ^ 0) << 4);  // s8 high bit folded below
        // store p and (n&1) info: recompute inline instead (cheap); keep base:
        w1b[q] = (uint32_t)(p * 128);
        w2b[q] = sm + W2_OFF + (uint32_t)(n * 512);
        w2sw[q] = (uint32_t)((n & 7) << 4);
    }
    uint32_t w1sw[4], w1hi[4];
    #pragma unroll
    for (int q = 0; q < 4; q++) {
        int n = nb + q * 16 + fr_row;
        w1sw[q] = (uint32_t)(((n >> 1) & 7) << 4);
        w1hi[q] = (uint32_t)((n & 1) << 6);        // (n&1)*4 segs = +64B pre-XOR
    }

    float acc[2][8][4];

    // ======================== persistent tile loop ===========================
    for (int tile = blockIdx.x; tile < NTILES; tile += GRID) {
        __syncthreads();                   // prev tile's h reads fully done

        // ---- stage x: LDG fp32 -> half, swizzled 256B rows ------------------
        {
            const float* xg = x + (size_t)tile * 16384;
            const int x_row = tid >> 2, x_q = tid & 3;
            const float4* p = (const float4*)(xg + x_row * 128 + x_q * 32);
            float4 v[8];
            #pragma unroll
            for (int jj = 0; jj < 8; jj++) v[jj] = p[jj];
            #pragma unroll
            for (int s4 = 0; s4 < 4; s4++) {
                __half2 h0 = __floats2half2_rn(v[s4 * 2].x, v[s4 * 2].y);
                __half2 h1 = __floats2half2_rn(v[s4 * 2].z, v[s4 * 2].w);
                __half2 h2 = __floats2half2_rn(v[s4 * 2 + 1].x, v[s4 * 2 + 1].y);
                __half2 h3 = __floats2half2_rn(v[s4 * 2 + 1].z, v[s4 * 2 + 1].w);
                uint4 u;
                u.x = *(uint32_t*)&h0; u.y = *(uint32_t*)&h1;
                u.z = *(uint32_t*)&h2; u.w = *(uint32_t*)&h3;
                int seg = x_q * 4 + s4;
                *(uint4*)(smem + HS_OFF + (uint32_t)(x_row * 256)
                          + (uint32_t)((seg ^ (x_row & 7)) << 4)) = u;
            }
        }
        CP_WAIT0();                        // W1 c0,c1 (+ W2 on first iter)
        __syncthreads();

        #pragma unroll
        for (int m = 0; m < 2; m++)
            #pragma unroll
            for (int n = 0; n < 8; n++)
                #pragma unroll
                for (int c = 0; c < 4; c++) acc[m][n][c] = 0.0f;

        // ---- layer 1: 4 K=32 chunks -----------------------------------------
        auto l1_chunk = [&](int cc, uint32_t slot) {
            #pragma unroll
            for (int k16 = 0; k16 < 2; k16++) {
                const uint32_t xseg4 = (uint32_t)((cc * 4 + k16 * 2 + fr_k8) << 4);
                uint32_t A0[4], A1[4];
                ldsm4(A0, xA0 + (xseg4 ^ xsw0));
                ldsm4(A1, xA1 + (xseg4 ^ xsw1));
                const uint32_t kseg = (uint32_t)((k16 * 2 + fr_k8) << 4);
                #pragma unroll
                for (int q = 0; q < 4; q++) {
                    uint32_t B[4];
                    ldsm4(B, slot + w1b[q] + (((w1hi[q] | kseg)) ^ w1sw[q]));
                    mma16(acc[0][2 * q],     A0, B[0], B[2]);
                    mma16(acc[0][2 * q + 1], A0, B[1], B[3]);
                    mma16(acc[1][2 * q],     A1, B[0], B[2]);
                    mma16(acc[1][2 * q + 1], A1, B[1], B[3]);
                }
            }
        };
        l1_chunk(0, sm + R0_OFF);
        __syncthreads();                   // c0 consumed by all
        issue_w1(2, sm + R0_OFF);
        l1_chunk(1, sm + R1_OFF);
        __syncthreads();                   // c1 consumed by all
        issue_w1(3, sm + R1_OFF);
        CP_WAIT1(); __syncthreads();       // c2 visible
        l1_chunk(2, sm + R0_OFF);
        CP_WAIT0(); __syncthreads();       // c3 visible (c2 reads done)
        l1_chunk(3, sm + R1_OFF);
        __syncthreads();                   // c3 + x reads done; hs writable

        // ---- h = half(relu(acc + b_emb)) -> hs (512B rows, swizzled) --------
        #pragma unroll
        for (int m = 0; m < 2; m++) {
            const int r0 = mw * 32 + m * 16 + g;
            #pragma unroll
            for (int q = 0; q < 8; q++) {
                int col = nb + q * 8 + 2 * tg;
                float b0v = sbe[col], b1v = sbe[col + 1];
                __half2 v0 = __floats2half2_rn(fmaxf(acc[m][q][0] + b0v, 0.0f),
                                               fmaxf(acc[m][q][1] + b1v, 0.0f));
                __half2 v1 = __floats2half2_rn(fmaxf(acc[m][q][2] + b0v, 0.0f),
                                               fmaxf(acc[m][q][3] + b1v, 0.0f));
                int seg = col >> 3;
                uint32_t a0 = sm + HS_OFF + (uint32_t)(r0 * 512)
                            + (uint32_t)((seg ^ (r0 & 7)) << 4) + (uint32_t)(4 * tg);
                uint32_t a1 = sm + HS_OFF + (uint32_t)((r0 + 8) * 512)
                            + (uint32_t)((seg ^ ((r0 + 8) & 7)) << 4) + (uint32_t)(4 * tg);
                *(__half2*)(smem + (a0 - sm)) = v0;
                *(__half2*)(smem + (a1 - sm)) = v1;
            }
        }
        // prefetch next tile's W1 c0,c1 (slots fully consumed)
        issue_w1(0, sm + R0_OFF);
        issue_w1(1, sm + R1_OFF);
        __syncthreads();                   // h visible

        #pragma unroll
        for (int m = 0; m < 2; m++)
            #pragma unroll
            for (int n = 0; n < 8; n++)
                #pragma unroll
                for (int c = 0; c < 4; c++) acc[m][n][c] = 0.0f;

        // ---- layer 2: 8 K=32 blocks, W2 resident, BARRIER-FREE --------------
        #pragma unroll
        for (int c32 = 0; c32 < 8; c32++) {
            #pragma unroll
            for (int k16 = 0; k16 < 2; k16++) {
                const uint32_t seg4 = (uint32_t)((c32 * 4 + k16 * 2 + fr_k8) << 4);
                uint32_t A0[4], A1[4];
                ldsm4(A0, hA0 + (seg4 ^ xsw0));
                ldsm4(A1, hA1 + (seg4 ^ xsw1));
                #pragma unroll
                for (int q = 0; q < 4; q++) {
                    uint32_t B[4];
                    ldsm4(B, w2b[q] + (seg4 ^ w2sw[q]));
                    mma16(acc[0][2 * q],     A0, B[0], B[2]);
                    mma16(acc[0][2 * q + 1], A0, B[1], B[3]);
                    mma16(acc[1][2 * q],     A1, B[0], B[2]);
                    mma16(acc[1][2 * q + 1], A1, B[1], B[3]);
                }
            }
        }

        // ---- epilogue: all in registers (mean/logvar pairs per thread) ------
        {
            const float* eg = eps + (size_t)tile * 16384;
            float* oz = out + (size_t)tile * 16384;
            float* om = out + 67108864ull + (size_t)tile * 16384;
            float* ol = out + 134217728ull + (size_t)tile * 16384;
            #pragma unroll
            for (int m = 0; m < 2; m++) {
                const int rA = mw * 32 + m * 16 + g, rB = rA + 8;
                #pragma unroll
                for (int q = 0; q < 8; q++) {
                    int c = (nb >> 1) + q * 4 + tg;
                    float bmv = sbm[c], blv = sbl[c];
                    float mv0 = acc[m][q][0] + bmv;
                    float lv0 = acc[m][q][1] + blv;
                    float mv1 = acc[m][q][2] + bmv;
                    float lv1 = acc[m][q][3] + blv;
                    float z0 = fmaf(__expf(0.5f * lv0), eg[rA * 128 + c], mv0);
                    float z1 = fmaf(__expf(0.5f * lv1), eg[rB * 128 + c], mv1);
                    oz[rA * 128 + c] = z0;  om[rA * 128 + c] = mv0;  ol[rA * 128 + c] = lv0;
                    oz[rB * 128 + c] = z1;  om[rB * 128 + c] = mv1;  ol[rB * 128 + c] = lv1;
                }
            }
        }
    }
}

// ---------------------------------------------------------------------------

extern "C" void kernel_launch(void* const* d_in, const int* in_sizes, int n_in,
                              void* d_out, int out_size) {
    const float* x   = (const float*)d_in[0];
    const float* eps = (const float*)d_in[1];
    const float* We  = (const float*)d_in[2];
    const float* be  = (const float*)d_in[3];
    const float* Wm  = (const float*)d_in[4];
    const float* bm  = (const float*)d_in[5];
    const float* Wl  = (const float*)d_in[6];
    const float* bl  = (const float*)d_in[7];
    float* out = (float*)d_out;

    cudaFuncSetAttribute(gauss_kernel, cudaFuncAttributeMaxDynamicSharedMemorySize, SMEM_TOTAL);
    prep_kernel<<<384, 256>>>(We, Wm, Wl);
    gauss_kernel<<<GRID, 512, SMEM_TOTAL>>>(x, eps, be, bm, bl, out);
}

// round 12
// speedup vs baseline: 1.4159x; 1.4159x over previous
#include <cuda_runtime.h>
#include <cuda_fp16.h>
#include <cstdint>

// ============================================================================
// GaussianMLP fused — sm_103 plain target, fp16 mma.sync.m16n8k16.
// R12: R8 structure (512 thr, 4x4 warps, M32xN64, 3-slot K=32 cp.async ring)
//   + W2 interleaved at 8-col blocks -> register-only epilogue (no exchange,
//     no post-L2 barriers)
//   + eps staged to SMEM via cp.async at tile start (epilogue LDG removed).
// ============================================================================

#define NTILES 4096

__device__ __forceinline__ uint32_t smem_u32(const void* p) {
    uint32_t a;
    asm("{ .reg .u64 t; cvta.to.shared.u64 t, %1; cvt.u32.u64 %0, t; }" : "=r"(a) : "l"(p));
    return a;
}
__device__ __forceinline__ void mma16(float* c, const uint32_t* a, uint32_t b0, uint32_t b1) {
    asm volatile(
        "mma.sync.aligned.m16n8k16.row.col.f32.f16.f16.f32 "
        "{%0,%1,%2,%3},{%4,%5,%6,%7},{%8,%9},{%0,%1,%2,%3};"
        : "+f"(c[0]), "+f"(c[1]), "+f"(c[2]), "+f"(c[3])
        : "r"(a[0]), "r"(a[1]), "r"(a[2]), "r"(a[3]), "r"(b0), "r"(b1));
}
__device__ __forceinline__ void ldsm4(uint32_t* r, uint32_t addr) {
    asm volatile("ldmatrix.sync.aligned.m8n8.x4.shared.b16 {%0,%1,%2,%3}, [%4];"
                 : "=r"(r[0]), "=r"(r[1]), "=r"(r[2]), "=r"(r[3]) : "r"(addr));
}
#define CP16CG(dst, src) \
    asm volatile("cp.async.cg.shared.global [%0], [%1], 16;" :: "r"(dst), "l"(src))
#define CP_COMMIT() asm volatile("cp.async.commit_group;" ::: "memory")
#define CP_WAIT1()  asm volatile("cp.async.wait_group 1;" ::: "memory")
#define CP_WAIT0()  asm volatile("cp.async.wait_group 0;" ::: "memory")

// ---------------- pre-converted half weights, [n][k] -------------------------
__device__ __align__(16) __half g_wemb_h[256 * 128];
// W2 interleaved at 8-col blocks: n' block 2t -> W_mean cols [8t,8t+8),
//                                 n' block 2t+1 -> W_logvar cols [8t,8t+8)
__device__ __align__(16) __half g_w2_h[256 * 256];

__global__ void prep_kernel(const float* __restrict__ We,
                            const float* __restrict__ Wm,
                            const float* __restrict__ Wl) {
    int i = blockIdx.x * 256 + threadIdx.x;
    if (i < 32768) {
        int n = i >> 7, k = i & 127;
        g_wemb_h[i] = __float2half(We[k * 256 + n]);
    } else if (i < 98304) {
        int j = i - 32768;
        int np = j >> 8, k = j & 255;
        int c = ((np >> 4) << 3) | (np & 7);
        float v = ((np >> 3) & 1) ? Wl[k * 128 + c] : Wm[k * 128 + c];
        g_w2_h[j] = __float2half(v);
    }
}

// ---------------- SMEM map (219136 B) ----------------------------------------
#define HS_OFF    0u
#define XS0_OFF   67584u
#define XS1_OFF   77824u
#define RING_OFF  88064u
#define SLOT_SZ   20480u
#define SBE_OFF   149504u
#define SBM_OFF   150528u
#define SBL_OFF   151040u
#define ES_OFF    151552u           // eps fp32 [128][132] padded
#define SMEM_TOTAL 219136
#define HS_S 264          // halves
#define XW_S 40           // halves
#define ES_S 132          // floats

__global__ void __launch_bounds__(512, 1)
gauss_kernel(const float* __restrict__ x, const float* __restrict__ eps,
             const float* __restrict__ be, const float* __restrict__ bm,
             const float* __restrict__ bl, float* __restrict__ out) {
    extern __shared__ char smem[];
    const uint32_t sm = smem_u32(smem);
    float* sbe = (float*)(smem + SBE_OFF);
    float* sbm = (float*)(smem + SBM_OFF);
    float* sbl = (float*)(smem + SBL_OFF);

    const int tid  = threadIdx.x;
    const int wid  = tid >> 5, lane = tid & 31;
    const int g    = lane >> 2, tg = lane & 3;
    const int mw   = wid & 3;                 // M block (32 rows)
    const int nw   = wid >> 2;                // N block (64 n'-cols)
    const int nb   = nw * 64;
    const size_t tile = blockIdx.x;

    const int fr_row = lane & 15;
    const int fr_ko  = (lane & 16) ? 8 : 0;

    if (tid < 256) sbe[tid] = be[tid];
    if (tid < 128) { sbm[tid] = bm[tid]; sbl[tid] = bl[tid]; }

    const float* xg = x + tile * 16384;
    const int x_row = tid >> 2, x_q = tid & 3;

    const uint32_t xsb[2] = { sm + XS0_OFF, sm + XS1_OFF };

    auto issue_stage = [&](int i) {                  // W chunk, K=32 halves
        if (i >= 12) return;
        uint32_t base = sm + RING_OFF + (uint32_t)(i % 3) * SLOT_SZ;
        const __half* w = (i < 4) ? (g_wemb_h + i * 32) : (g_w2_h + (i - 4) * 32);
        const int rs = (i < 4) ? 128 : 256;
        const int row = tid >> 1, seg = (tid & 1) * 2;
        CP16CG(base + (uint32_t)(row * 80 + seg * 16),       w + row * rs + seg * 8);
        CP16CG(base + (uint32_t)(row * 80 + (seg + 1) * 16), w + row * rs + (seg + 1) * 8);
        CP_COMMIT();
    };
    auto ldg_x = [&](int s, float4& v0, float4& v1) {
        const float* p = xg + x_row * 128 + s * 32 + x_q * 8;
        v0 = *(const float4*)p;
        v1 = *(const float4*)(p + 4);
    };
    auto sts_x = [&](int s, const float4& v0, const float4& v1) {
        __half2 h0 = __floats2half2_rn(v0.x, v0.y);
        __half2 h1 = __floats2half2_rn(v0.z, v0.w);
        __half2 h2 = __floats2half2_rn(v1.x, v1.y);
        __half2 h3 = __floats2half2_rn(v1.z, v1.w);
        uint4 u;
        u.x = *(uint32_t*)&h0; u.y = *(uint32_t*)&h1;
        u.z = *(uint32_t*)&h2; u.w = *(uint32_t*)&h3;
        *(uint4*)(smem + (XS0_OFF + (uint32_t)(s & 1) * 10240u)
                  + (uint32_t)(x_row * 80 + x_q * 16)) = u;
    };

    float acc[2][8][4];
    #pragma unroll
    for (int m = 0; m < 2; m++)
        #pragma unroll
        for (int n = 0; n < 8; n++)
            #pragma unroll
            for (int c = 0; c < 4; c++) acc[m][n][c] = 0.0f;

    // prologue: W stages 0,1 then eps (own group; drained by stage waits)
    issue_stage(0);
    issue_stage(1);
    {
        const float* eg = eps + tile * 16384;
        #pragma unroll
        for (int j = 0; j < 8; j++) {
            int i4 = tid + j * 512;
            int r = i4 >> 5, c4 = i4 & 31;
            CP16CG(sm + ES_OFF + (uint32_t)(r * (ES_S * 4) + c4 * 16),
                   eg + r * 128 + c4 * 4);
        }
        CP_COMMIT();
    }
    float4 xr0, xr1;
    ldg_x(0, xr0, xr1);
    sts_x(0, xr0, xr1);
    ldg_x(1, xr0, xr1);

    // ======================= layer 1 (stages 0..3, K=32) =====================
    #pragma unroll 1
    for (int s = 0; s < 4; s++) {
        CP_WAIT1();
        __syncthreads();                 // W[s] + x[s] visible
        issue_stage(s + 2);
        if (s < 3) {
            sts_x(s + 1, xr0, xr1);
            if (s < 2) ldg_x(s + 2, xr0, xr1);
        }

        const uint32_t a_base = xsb[s & 1]
            + (uint32_t)((mw * 32 + fr_row) * XW_S + fr_ko) * 2u;
        const uint32_t b_base = sm + RING_OFF + (uint32_t)(s % 3) * SLOT_SZ
            + (uint32_t)((nb + fr_row) * XW_S + fr_ko) * 2u;
        #pragma unroll
        for (int kk = 0; kk < 2; kk++) {
            uint32_t A0[4], A1[4];
            ldsm4(A0, a_base + kk * 32u);
            ldsm4(A1, a_base + 1280u + kk * 32u);        // +16 rows
            #pragma unroll
            for (int q = 0; q < 4; q++) {
                uint32_t B[4];
                ldsm4(B, b_base + (uint32_t)(q * 16 * 80) + kk * 32u);
                mma16(acc[0][2 * q],     A0, B[0], B[2]);
                mma16(acc[0][2 * q + 1], A0, B[1], B[3]);
                mma16(acc[1][2 * q],     A1, B[0], B[2]);
                mma16(acc[1][2 * q + 1], A1, B[1], B[3]);
            }
        }
    }

    // ---- h = half(relu(acc + b_emb)) -> SMEM ----
    {
        #pragma unroll
        for (int m = 0; m < 2; m++) {
            const int r0 = mw * 32 + m * 16 + g;
            #pragma unroll
            for (int n = 0; n < 8; n++) {
                int col = nb + n * 8 + 2 * tg;
                float b0v = sbe[col], b1v = sbe[col + 1];
                __half2 v0 = __floats2half2_rn(fmaxf(acc[m][n][0] + b0v, 0.0f),
                                               fmaxf(acc[m][n][1] + b1v, 0.0f));
                __half2 v1 = __floats2half2_rn(fmaxf(acc[m][n][2] + b0v, 0.0f),
                                               fmaxf(acc[m][n][3] + b1v, 0.0f));
                *(__half2*)(smem + HS_OFF + (uint32_t)(r0 * HS_S + col) * 2u)       = v0;
                *(__half2*)(smem + HS_OFF + (uint32_t)((r0 + 8) * HS_S + col) * 2u) = v1;
            }
        }
    }
    #pragma unroll
    for (int m = 0; m < 2; m++)
        #pragma unroll
        for (int n = 0; n < 8; n++)
            #pragma unroll
            for (int c = 0; c < 4; c++) acc[m][n][c] = 0.0f;

    // ======================= layer 2 (stages 4..11) ==========================
    #pragma unroll 1
    for (int i = 4; i < 12; i++) {
        if (i == 11) { CP_WAIT0(); } else { CP_WAIT1(); }
        __syncthreads();                 // W[i] + (i==4: h tile) visible
        issue_stage(i + 2);

        const int c32 = i - 4;
        const uint32_t a_base = sm + HS_OFF
            + (uint32_t)((mw * 32 + fr_row) * HS_S + c32 * 32 + fr_ko) * 2u;
        const uint32_t b_base = sm + RING_OFF + (uint32_t)(i % 3) * SLOT_SZ
            + (uint32_t)((nb + fr_row) * XW_S + fr_ko) * 2u;
        #pragma unroll
        for (int kk = 0; kk < 2; kk++) {
            uint32_t A0[4], A1[4];
            ldsm4(A0, a_base + kk * 32u);
            ldsm4(A1, a_base + 8448u + kk * 32u);        // +16 rows (HS_S)
            #pragma unroll
            for (int q = 0; q < 4; q++) {
                uint32_t B[4];
                ldsm4(B, b_base + (uint32_t)(q * 16 * 80) + kk * 32u);
                mma16(acc[0][2 * q],     A0, B[0], B[2]);
                mma16(acc[0][2 * q + 1], A0, B[1], B[3]);
                mma16(acc[1][2 * q],     A1, B[0], B[2]);
                mma16(acc[1][2 * q + 1], A1, B[1], B[3]);
            }
        }
    }
    // NOTE: no barrier needed — stage-11 top barrier followed CP_WAIT0, so the
    // eps SMEM tile (cp.async) is complete and visible to all threads.

    // ====== epilogue: register-only (interleaved W2 pairs mean/logvar) =======
    {
        const float* es = (const float*)(smem + ES_OFF);
        float* oz = out + tile * 16384;
        float* om = out + 67108864ull + tile * 16384;
        float* ol = out + 134217728ull + tile * 16384;
        #pragma unroll
        for (int m = 0; m < 2; m++) {
            const int rA = mw * 32 + m * 16 + g, rB = rA + 8;
            #pragma unroll
            for (int e = 0; e < 4; e++) {
                // acc[m][2e]   = mean block  t = 4*nw + e (cols 8t + 2tg, +1)
                // acc[m][2e+1] = logvar block, same cols/rows
                const int c = 8 * (4 * nw + e) + 2 * tg;
                float bm0 = sbm[c], bm1 = sbm[c + 1];
                float bl0 = sbl[c], bl1 = sbl[c + 1];
                float me0 = acc[m][2 * e][0] + bm0, me1 = acc[m][2 * e][1] + bm1;
                float me2 = acc[m][2 * e][2] + bm0, me3 = acc[m][2 * e][3] + bm1;
                float lv0 = acc[m][2 * e + 1][0] + bl0, lv1 = acc[m][2 * e + 1][1] + bl1;
                float lv2 = acc[m][2 * e + 1][2] + bl0, lv3 = acc[m][2 * e + 1][3] + bl1;
                float2 eA = *(const float2*)&es[rA * ES_S + c];
                float2 eB = *(const float2*)&es[rB * ES_S + c];
                float2 z0, z1;
                z0.x = fmaf(__expf(0.5f * lv0), eA.x, me0);
                z0.y = fmaf(__expf(0.5f * lv1), eA.y, me1);
                z1.x = fmaf(__expf(0.5f * lv2), eB.x, me2);
                z1.y = fmaf(__expf(0.5f * lv3), eB.y, me3);
                *(float2*)&oz[rA * 128 + c] = z0;
                *(float2*)&oz[rB * 128 + c] = z1;
                *(float2*)&om[rA * 128 + c] = make_float2(me0, me1);
                *(float2*)&om[rB * 128 + c] = make_float2(me2, me3);
                *(float2*)&ol[rA * 128 + c] = make_float2(lv0, lv1);
                *(float2*)&ol[rB * 128 + c] = make_float2(lv2, lv3);
            }
        }
    }
}

// ---------------------------------------------------------------------------

extern "C" void kernel_launch(void* const* d_in, const int* in_sizes, int n_in,
                              void* d_out, int out_size) {
    const float* x   = (const float*)d_in[0];
    const float* eps = (const float*)d_in[1];
    const float* We  = (const float*)d_in[2];
    const float* be  = (const float*)d_in[3];
    const float* Wm  = (const float*)d_in[4];
    const float* bm  = (const float*)d_in[5];
    const float* Wl  = (const float*)d_in[6];
    const float* bl  = (const float*)d_in[7];
    float* out = (float*)d_out;

    cudaFuncSetAttribute(gauss_kernel, cudaFuncAttributeMaxDynamicSharedMemorySize, SMEM_TOTAL);
    prep_kernel<<<384, 256>>>(We, Wm, Wl);
    gauss_kernel<<<NTILES, 512, SMEM_TOTAL>>>(x, eps, be, bm, bl, out);
}

// round 13
// speedup vs baseline: 1.4453x; 1.0208x over previous
#include <cuda_runtime.h>
#include <cuda_fp16.h>
#include <cstdint>

// ============================================================================
// GaussianMLP fused — sm_103 plain target, fp16 mma.sync.m16n8k16.
// R13: 512 thr, 4x4 warps, M32xN64; K=64 mega-stages (6 total: 2 L1 + 4 L2),
//      3-slot cp.async ring (44KB slots, 176B conflict-free rows), interleaved
//      W2 -> register-only epilogue with direct eps LDG. Uniform commit groups.
// ============================================================================

#define NTILES 4096

__device__ __forceinline__ uint32_t smem_u32(const void* p) {
    uint32_t a;
    asm("{ .reg .u64 t; cvta.to.shared.u64 t, %1; cvt.u32.u64 %0, t; }" : "=r"(a) : "l"(p));
    return a;
}
__device__ __forceinline__ void mma16(float* c, const uint32_t* a, uint32_t b0, uint32_t b1) {
    asm volatile(
        "mma.sync.aligned.m16n8k16.row.col.f32.f16.f16.f32 "
        "{%0,%1,%2,%3},{%4,%5,%6,%7},{%8,%9},{%0,%1,%2,%3};"
        : "+f"(c[0]), "+f"(c[1]), "+f"(c[2]), "+f"(c[3])
        : "r"(a[0]), "r"(a[1]), "r"(a[2]), "r"(a[3]), "r"(b0), "r"(b1));
}
__device__ __forceinline__ void ldsm4(uint32_t* r, uint32_t addr) {
    asm volatile("ldmatrix.sync.aligned.m8n8.x4.shared.b16 {%0,%1,%2,%3}, [%4];"
                 : "=r"(r[0]), "=r"(r[1]), "=r"(r[2]), "=r"(r[3]) : "r"(addr));
}
#define CP16CG(dst, src) \
    asm volatile("cp.async.cg.shared.global [%0], [%1], 16;" :: "r"(dst), "l"(src))
#define CP_COMMIT() asm volatile("cp.async.commit_group;" ::: "memory")
#define CP_WAIT1()  asm volatile("cp.async.wait_group 1;" ::: "memory")
#define CP_WAIT0()  asm volatile("cp.async.wait_group 0;" ::: "memory")

// ---------------- pre-converted half weights, [n][k] -------------------------
__device__ __align__(16) __half g_wemb_h[256 * 128];
// W2 interleaved at 8-col blocks: n' block 2t -> W_mean cols [8t,8t+8),
//                                 n' block 2t+1 -> W_logvar cols [8t,8t+8)
__device__ __align__(16) __half g_w2_h[256 * 256];

__global__ void prep_kernel(const float* __restrict__ We,
                            const float* __restrict__ Wm,
                            const float* __restrict__ Wl) {
    int i = blockIdx.x * 256 + threadIdx.x;
    if (i < 32768) {
        int n = i >> 7, k = i & 127;
        g_wemb_h[i] = __float2half(We[k * 256 + n]);
    } else if (i < 98304) {
        int j = i - 32768;
        int np = j >> 8, k = j & 255;
        int c = ((np >> 4) << 3) | (np & 7);
        float v = ((np >> 3) & 1) ? Wl[k * 128 + c] : Wm[k * 128 + c];
        g_w2_h[j] = __float2half(v);
    }
}

// ---------------- SMEM map (204800 B) ----------------------------------------
// hs   : h half tile [128][264] (528B rows)       67584
//        (x chunks overlaid: 2 x [128][88] = 45056, live only during L1)
// ring : 3 x 45056  W chunks [256][88] (176B rows, 128B data + pad)
// bias : 2048
#define HS_OFF    0u
#define XS0_OFF   0u
#define XS1_OFF   22528u
#define RING_OFF  67584u
#define SLOT_SZ   45056u
#define SBE_OFF   202752u
#define SBM_OFF   203776u
#define SBL_OFF   204288u
#define SMEM_TOTAL 204800
#define HS_SB 528u        // h row stride (bytes)
#define XW_SB 176u        // ring / x-chunk row stride (bytes)

__global__ void __launch_bounds__(512, 1)
gauss_kernel(const float* __restrict__ x, const float* __restrict__ eps,
             const float* __restrict__ be, const float* __restrict__ bm,
             const float* __restrict__ bl, float* __restrict__ out) {
    extern __shared__ char smem[];
    const uint32_t sm = smem_u32(smem);
    float* sbe = (float*)(smem + SBE_OFF);
    float* sbm = (float*)(smem + SBM_OFF);
    float* sbl = (float*)(smem + SBL_OFF);

    const int tid  = threadIdx.x;
    const int wid  = tid >> 5, lane = tid & 31;
    const int g    = lane >> 2, tg = lane & 3;
    const int mw   = wid & 3;                 // M block (32 rows)
    const int nw   = wid >> 2;                // N block (64 n'-cols)
    const int nb   = nw * 64;
    const size_t tile = blockIdx.x;

    const int fr_row = lane & 15;
    const uint32_t fr_kb = (lane & 16) ? 16u : 0u;   // k byte offset

    if (tid < 256) sbe[tid] = be[tid];
    if (tid < 128) { sbm[tid] = bm[tid]; sbl[tid] = bl[tid]; }

    const float* xg = x + tile * 16384;

    // ---- stage issuer: K=64 weight chunk -> ring slot (one commit) ----------
    auto issue_stage = [&](int i) {
        if (i >= 6) return;
        uint32_t base = sm + RING_OFF + (uint32_t)(i % 3) * SLOT_SZ;
        const __half* w = (i < 2) ? (g_wemb_h + i * 64) : (g_w2_h + (i - 2) * 64);
        const int rs = (i < 2) ? 128 : 256;
        const int row = tid >> 1, h = tid & 1;       // 256 rows x 2 thr
        const __half* src = w + row * rs + h * 32;
        uint32_t dst = base + (uint32_t)row * XW_SB + (uint32_t)(h * 64);
        CP16CG(dst,       src);
        CP16CG(dst + 16u, src + 8);
        CP16CG(dst + 32u, src + 16);
        CP16CG(dst + 48u, src + 24);
        CP_COMMIT();
    };
    // x chunk staging: LDG fp32 -> half -> STS (176B rows)
    const int x_row = tid >> 2, x_q = tid & 3;       // 128 rows x 4 thr
    float4 xr[4];
    auto ldg_x = [&](int s) {
        const float4* p = (const float4*)(xg + x_row * 128 + s * 64 + x_q * 16);
        xr[0] = p[0]; xr[1] = p[1]; xr[2] = p[2]; xr[3] = p[3];
    };
    auto sts_x = [&](int s) {
        uint4 u0, u1;
        {
            __half2 h0 = __floats2half2_rn(xr[0].x, xr[0].y);
            __half2 h1 = __floats2half2_rn(xr[0].z, xr[0].w);
            __half2 h2 = __floats2half2_rn(xr[1].x, xr[1].y);
            __half2 h3 = __floats2half2_rn(xr[1].z, xr[1].w);
            u0.x = *(uint32_t*)&h0; u0.y = *(uint32_t*)&h1;
            u0.z = *(uint32_t*)&h2; u0.w = *(uint32_t*)&h3;
        }
        {
            __half2 h0 = __floats2half2_rn(xr[2].x, xr[2].y);
            __half2 h1 = __floats2half2_rn(xr[2].z, xr[2].w);
            __half2 h2 = __floats2half2_rn(xr[3].x, xr[3].y);
            __half2 h3 = __floats2half2_rn(xr[3].z, xr[3].w);
            u1.x = *(uint32_t*)&h0; u1.y = *(uint32_t*)&h1;
            u1.z = *(uint32_t*)&h2; u1.w = *(uint32_t*)&h3;
        }
        uint32_t base = (XS0_OFF + (uint32_t)(s & 1) * 22528u)
                      + (uint32_t)x_row * XW_SB + (uint32_t)(x_q * 32);
        *(uint4*)(smem + base)       = u0;
        *(uint4*)(smem + base + 16u) = u1;
    };

    float acc[2][8][4];
    #pragma unroll
    for (int m = 0; m < 2; m++)
        #pragma unroll
        for (int n = 0; n < 8; n++)
            #pragma unroll
            for (int c = 0; c < 4; c++) acc[m][n][c] = 0.0f;

    // prologue: W stages 0,1 in flight; x chunk 0 staged, chunk 1 in regs
    issue_stage(0);
    issue_stage(1);
    ldg_x(0); sts_x(0);
    ldg_x(1);

    // ======================= layer 1 (stages 0..1, K=64) =====================
    #pragma unroll 1
    for (int s = 0; s < 2; s++) {
        CP_WAIT1();
        __syncthreads();                 // W[s] + x[s] visible; slot s-1 free
        issue_stage(s + 2);
        if (s == 0) sts_x(1);

        const uint32_t a_base = sm + (XS0_OFF + (uint32_t)(s & 1) * 22528u)
            + (uint32_t)(mw * 32 + fr_row) * XW_SB + fr_kb;
        const uint32_t b_base = sm + RING_OFF + (uint32_t)(s % 3) * SLOT_SZ
            + (uint32_t)(nb + fr_row) * XW_SB + fr_kb;
        #pragma unroll
        for (int kk = 0; kk < 4; kk++) {
            uint32_t A0[4], A1[4];
            ldsm4(A0, a_base + (uint32_t)(kk * 32));
            ldsm4(A1, a_base + 16u * XW_SB + (uint32_t)(kk * 32));
            #pragma unroll
            for (int q = 0; q < 4; q++) {
                uint32_t B[4];
                ldsm4(B, b_base + (uint32_t)(q * 16) * XW_SB + (uint32_t)(kk * 32));
                mma16(acc[0][2 * q],     A0, B[0], B[2]);
                mma16(acc[0][2 * q + 1], A0, B[1], B[3]);
                mma16(acc[1][2 * q],     A1, B[0], B[2]);
                mma16(acc[1][2 * q + 1], A1, B[1], B[3]);
            }
        }
    }
    __syncthreads();                     // all x reads done -> hs writable

    // ---- h = half(relu(acc + b_emb)) -> hs ----
    {
        #pragma unroll
        for (int m = 0; m < 2; m++) {
            const int r0 = mw * 32 + m * 16 + g;
            #pragma unroll
            for (int n = 0; n < 8; n++) {
                int col = nb + n * 8 + 2 * tg;
                float b0v = sbe[col], b1v = sbe[col + 1];
                __half2 v0 = __floats2half2_rn(fmaxf(acc[m][n][0] + b0v, 0.0f),
                                               fmaxf(acc[m][n][1] + b1v, 0.0f));
                __half2 v1 = __floats2half2_rn(fmaxf(acc[m][n][2] + b0v, 0.0f),
                                               fmaxf(acc[m][n][3] + b1v, 0.0f));
                *(__half2*)(smem + HS_OFF + (uint32_t)r0 * HS_SB + (uint32_t)(col * 2))       = v0;
                *(__half2*)(smem + HS_OFF + (uint32_t)(r0 + 8) * HS_SB + (uint32_t)(col * 2)) = v1;
            }
        }
    }
    #pragma unroll
    for (int m = 0; m < 2; m++)
        #pragma unroll
        for (int n = 0; n < 8; n++)
            #pragma unroll
            for (int c = 0; c < 4; c++) acc[m][n][c] = 0.0f;

    // ======================= layer 2 (stages 2..5, K=64) =====================
    #pragma unroll 1
    for (int s = 2; s < 6; s++) {
        if (s == 5) { CP_WAIT0(); } else { CP_WAIT1(); }
        __syncthreads();                 // W[s] + (s==2: h tile) visible
        issue_stage(s + 2);

        const uint32_t a_base = sm + HS_OFF
            + (uint32_t)(mw * 32 + fr_row) * HS_SB + (uint32_t)((s - 2) * 128) + fr_kb;
        const uint32_t b_base = sm + RING_OFF + (uint32_t)(s % 3) * SLOT_SZ
            + (uint32_t)(nb + fr_row) * XW_SB + fr_kb;
        #pragma unroll
        for (int kk = 0; kk < 4; kk++) {
            uint32_t A0[4], A1[4];
            ldsm4(A0, a_base + (uint32_t)(kk * 32));
            ldsm4(A1, a_base + 16u * HS_SB + (uint32_t)(kk * 32));
            #pragma unroll
            for (int q = 0; q < 4; q++) {
                uint32_t B[4];
                ldsm4(B, b_base + (uint32_t)(q * 16) * XW_SB + (uint32_t)(kk * 32));
                mma16(acc[0][2 * q],     A0, B[0], B[2]);
                mma16(acc[0][2 * q + 1], A0, B[1], B[3]);
                mma16(acc[1][2 * q],     A1, B[0], B[2]);
                mma16(acc[1][2 * q + 1], A1, B[1], B[3]);
            }
        }
    }

    // ====== epilogue: register-only (interleaved W2 pairs mean/logvar) =======
    {
        const float* eg = eps + tile * 16384;
        float* oz = out + tile * 16384;
        float* om = out + 67108864ull + tile * 16384;
        float* ol = out + 134217728ull + tile * 16384;
        #pragma unroll
        for (int m = 0; m < 2; m++) {
            const int rA = mw * 32 + m * 16 + g, rB = rA + 8;
            // batch eps loads first (MLP overlap)
            float2 eA[4], eB[4];
            #pragma unroll
            for (int e = 0; e < 4; e++) {
                const int c = 8 * (4 * nw + e) + 2 * tg;
                eA[e] = *(const float2*)&eg[rA * 128 + c];
                eB[e] = *(const float2*)&eg[rB * 128 + c];
            }
            #pragma unroll
            for (int e = 0; e < 4; e++) {
                const int c = 8 * (4 * nw + e) + 2 * tg;
                float bm0 = sbm[c], bm1 = sbm[c + 1];
                float bl0 = sbl[c], bl1 = sbl[c + 1];
                float me0 = acc[m][2 * e][0] + bm0, me1 = acc[m][2 * e][1] + bm1;
                float me2 = acc[m][2 * e][2] + bm0, me3 = acc[m][2 * e][3] + bm1;
                float lv0 = acc[m][2 * e + 1][0] + bl0, lv1 = acc[m][2 * e + 1][1] + bl1;
                float lv2 = acc[m][2 * e + 1][2] + bl0, lv3 = acc[m][2 * e + 1][3] + bl1;
                float2 z0, z1;
                z0.x = fmaf(__expf(0.5f * lv0), eA[e].x, me0);
                z0.y = fmaf(__expf(0.5f * lv1), eA[e].y, me1);
                z1.x = fmaf(__expf(0.5f * lv2), eB[e].x, me2);
                z1.y = fmaf(__expf(0.5f * lv3), eB[e].y, me3);
                *(float2*)&oz[rA * 128 + c] = z0;
                *(float2*)&oz[rB * 128 + c] = z1;
                *(float2*)&om[rA * 128 + c] = make_float2(me0, me1);
                *(float2*)&om[rB * 128 + c] = make_float2(me2, me3);
                *(float2*)&ol[rA * 128 + c] = make_float2(lv0, lv1);
                *(float2*)&ol[rB * 128 + c] = make_float2(lv2, lv3);
            }
        }
    }
}

// ---------------------------------------------------------------------------

extern "C" void kernel_launch(void* const* d_in, const int* in_sizes, int n_in,
                              void* d_out, int out_size) {
    const float* x   = (const float*)d_in[0];
    const float* eps = (const float*)d_in[1];
    const float* We  = (const float*)d_in[2];
    const float* be  = (const float*)d_in[3];
    const float* Wm  = (const float*)d_in[4];
    const float* bm  = (const float*)d_in[5];
    const float* Wl  = (const float*)d_in[6];
    const float* bl  = (const float*)d_in[7];
    float* out = (float*)d_out;

    cudaFuncSetAttribute(gauss_kernel, cudaFuncAttributeMaxDynamicSharedMemorySize, SMEM_TOTAL);
    prep_kernel<<<384, 256>>>(We, Wm, Wl);
    gauss_kernel<<<NTILES, 512, SMEM_TOTAL>>>(x, eps, be, bm, bl, out);
}